// round 12
// baseline (speedup 1.0000x reference)
#include <cuda_runtime.h>
#include <cuda_fp16.h>
#include <cstdint>

#define BATCH 16384
#define IN_F  512

// Ping-pong scratch (raw, reinterpreted as half or float) + fp16 weights.
__device__ float g_buf0[BATCH * 2048];
__device__ float g_buf1[BATCH * 2048];
__device__ float g_w1[2048 * 512];
__device__ float g_w2[2048 * 2048];
__device__ float g_w3[1024 * 2048];
__device__ float g_w4[512 * 1024];

__device__ __forceinline__ uint32_t smem_u32(const void* p) {
    uint32_t a;
    asm("{ .reg .u64 t; cvta.to.shared.u64 t, %1; cvt.u32.u64 %0, t; }"
        : "=r"(a) : "l"(p));
    return a;
}

// ---------------------------------------------------------------------------
// Weight convert: float -> half, all four weight matrices in one launch.
// ---------------------------------------------------------------------------
#define N4_W1 (2048 * 512 / 4)
#define N4_W2 (2048 * 2048 / 4)
#define N4_W3 (1024 * 2048 / 4)
#define N4_W4 (512 * 1024 / 4)
#define N4_TOTAL (N4_W1 + N4_W2 + N4_W3 + N4_W4)
__global__ void cvt_all_kernel(const float* __restrict__ W1,
                               const float* __restrict__ W2,
                               const float* __restrict__ W3,
                               const float* __restrict__ W4,
                               __half* __restrict__ o1, __half* __restrict__ o2,
                               __half* __restrict__ o3, __half* __restrict__ o4) {
    int i = blockIdx.x * blockDim.x + threadIdx.x;
    const float* in; __half* out; int off;
    if (i < N4_W1)                      { in = W1; out = o1; off = i; }
    else if (i < N4_W1 + N4_W2)         { in = W2; out = o2; off = i - N4_W1; }
    else if (i < N4_W1 + N4_W2 + N4_W3) { in = W3; out = o3; off = i - N4_W1 - N4_W2; }
    else                                { in = W4; out = o4; off = i - N4_W1 - N4_W2 - N4_W3; }
    float4 v = ((const float4*)in)[off];
    __half2 h0 = __floats2half2_rn(v.x, v.y);
    __half2 h1 = __floats2half2_rn(v.z, v.w);
    ((uint2*)out)[off] = make_uint2(*(uint32_t*)&h0, *(uint32_t*)&h1);
}

// ---------------------------------------------------------------------------
// Cross layer: h = half( x * (x . cross_w) + cross_b + x )  (one warp per row)
// ---------------------------------------------------------------------------
__global__ void cross_kernel(const float* __restrict__ x,
                             const float* __restrict__ cw,
                             const float* __restrict__ cb,
                             __half* __restrict__ out) {
    int gw   = (blockIdx.x * blockDim.x + threadIdx.x) >> 5;
    int lane = threadIdx.x & 31;
    if (gw >= BATCH) return;
    const float4* xr  = (const float4*)(x + (size_t)gw * IN_F);
    const float4* cwr = (const float4*)cw;
    float4 xv[4];
    float s = 0.f;
#pragma unroll
    for (int c = 0; c < 4; c++) {
        xv[c] = xr[c * 32 + lane];
        float4 w = cwr[c * 32 + lane];
        s += xv[c].x * w.x + xv[c].y * w.y + xv[c].z * w.z + xv[c].w * w.w;
    }
#pragma unroll
    for (int o = 16; o > 0; o >>= 1) s += __shfl_xor_sync(0xffffffffu, s, o);
    const float4* cbr = (const float4*)cb;
    uint2* outr = (uint2*)(out + (size_t)gw * IN_F);
#pragma unroll
    for (int c = 0; c < 4; c++) {
        float4 b = cbr[c * 32 + lane];
        __half2 h0 = __floats2half2_rn(fmaf(xv[c].x, s, b.x) + xv[c].x,
                                       fmaf(xv[c].y, s, b.y) + xv[c].y);
        __half2 h1 = __floats2half2_rn(fmaf(xv[c].z, s, b.z) + xv[c].z,
                                       fmaf(xv[c].w, s, b.w) + xv[c].w);
        outr[c * 32 + lane] = make_uint2(*(uint32_t*)&h0, *(uint32_t*)&h1);
    }
}

// ---------------------------------------------------------------------------
// FP16 tensor-core GEMM (fp32 accum), cp.async 3-stage + ldmatrix + SW128,
// with two-deep register fragment double-buffering in the k-step loop.
//   MODE 0: C = relu(A @ W^T + bias) stored as half.
//   MODE 1: partial[cta_x*BATCH + row] = relu(A @ W^T + bias) . wo_slice
// BM=BN=128, BK=64 (128B rows, SW128); 128 threads, 4 warps (2m x 2n),
// warp tile 64x64, m16n8k16. 96KB smem -> 2 CTAs/SM.
// ---------------------------------------------------------------------------
#define BM 128
#define BN 128
#define BK 64
#define NSTAGE 3
#define TILE_BYTES (BM * 128)                    // 16384 per operand
#define STAGE_BYTES (2 * TILE_BYTES)             // 32768
#define SMEM_BYTES (NSTAGE * STAGE_BYTES)        // 98304

#define MMA_F16(c, a, b)                                                      \
    asm volatile(                                                             \
        "mma.sync.aligned.m16n8k16.row.col.f32.f16.f16.f32 "                  \
        "{%0,%1,%2,%3},{%4,%5,%6,%7},{%8,%9},{%0,%1,%2,%3};"                  \
        : "+f"(c[0]), "+f"(c[1]), "+f"(c[2]), "+f"(c[3])                      \
        : "r"(a[0]), "r"(a[1]), "r"(a[2]), "r"(a[3]), "r"(b[0]), "r"(b[1]))

#define LDSM4(r0, r1, r2, r3, addr)                                           \
    asm volatile("ldmatrix.sync.aligned.m8n8.x4.shared.b16 {%0,%1,%2,%3}, [%4];" \
                 : "=r"(r0), "=r"(r1), "=r"(r2), "=r"(r3) : "r"(addr))

#define CP16(dst, src)                                                        \
    asm volatile("cp.async.cg.shared.global [%0], [%1], 16;"                  \
                 :: "r"(dst), "l"(src))

// SW128: 16B chunk c (0..7) of 128B row r -> byte offset
__device__ __forceinline__ uint32_t swz(int r, int c) {
    return (uint32_t)(r * 128 + ((c ^ (r & 7)) * 16));
}

template <int MODE>
__global__ __launch_bounds__(128, 2)
void gemm_f16(const __half* __restrict__ A, const __half* __restrict__ W,
              const float* __restrict__ bias, void* __restrict__ Cout,
              const float* __restrict__ wo, int K, int N) {
    extern __shared__ char smem[];
    const uint32_t sbase = smem_u32(smem);
    const int tid = threadIdx.x;
    const int warp = tid >> 5, lane = tid & 31;
    const int wm = warp >> 1, wn = warp & 1;     // 2x2 grid of 64x64 tiles
    const int gid = lane >> 2, tg = lane & 3;
    const int row0 = blockIdx.y * BM;
    const int col0 = blockIdx.x * BN;

    // cp.async producer coords
    const int pr = tid >> 3;
    const int pc = tid & 7;
    const __half* Abase = A + (size_t)(row0 + pr) * K + pc * 8;
    const __half* Wbase = W + (size_t)(col0 + pr) * K + pc * 8;
    const uint32_t pd = swz(pr, pc);

    // ldmatrix lane coords
    const int arowA = wm * 64 + (lane & 15);                         // + 16*mi
    const int acA   = lane >> 4;                                     // + 2*ks
    const int arowB = wn * 64 + (lane & 7) + ((lane & 16) ? 8 : 0);  // + 16*j
    const int acB   = (lane & 8) ? 1 : 0;                            // + 2*ks

    const int T = K / BK;

#define ISSUE_STAGE(kt)                                                       \
    do {                                                                      \
        uint32_t _sA = sbase + ((kt) % NSTAGE) * STAGE_BYTES;                 \
        uint32_t _sB = _sA + TILE_BYTES;                                      \
        const __half* _Ag = Abase + (size_t)(kt) * BK;                        \
        const __half* _Wg = Wbase + (size_t)(kt) * BK;                        \
        _Pragma("unroll")                                                     \
        for (int i = 0; i < 8; i++) {                                         \
            CP16(_sA + pd + i * 2048, _Ag + (size_t)(16 * i) * K);            \
            CP16(_sB + pd + i * 2048, _Wg + (size_t)(16 * i) * K);            \
        }                                                                     \
        asm volatile("cp.async.commit_group;" ::: "memory");                  \
    } while (0)

#define LOAD_FRAGS(buf, ks)                                                   \
    do {                                                                      \
        _Pragma("unroll")                                                     \
        for (int mi = 0; mi < 4; mi++)                                        \
            LDSM4(a[buf][mi][0], a[buf][mi][1], a[buf][mi][2], a[buf][mi][3], \
                  sA + swz(arowA + 16 * mi, (ks) * 2 + acA));                 \
        _Pragma("unroll")                                                     \
        for (int j = 0; j < 4; j++)                                           \
            LDSM4(b[buf][2 * j][0], b[buf][2 * j][1],                         \
                  b[buf][2 * j + 1][0], b[buf][2 * j + 1][1],                 \
                  sB + swz(arowB + 16 * j, (ks) * 2 + acB));                  \
    } while (0)

    float acc[4][8][4];
#pragma unroll
    for (int mi = 0; mi < 4; mi++)
#pragma unroll
        for (int ni = 0; ni < 8; ni++)
#pragma unroll
            for (int e = 0; e < 4; e++) acc[mi][ni][e] = 0.f;

    ISSUE_STAGE(0);
    ISSUE_STAGE(1);

    for (int kt = 0; kt < T; kt++) {
        if (kt + 1 < T)
            asm volatile("cp.async.wait_group 1;" ::: "memory");
        else
            asm volatile("cp.async.wait_group 0;" ::: "memory");
        __syncthreads();

        if (kt + 2 < T) ISSUE_STAGE(kt + 2);

        const uint32_t sA = sbase + (kt % NSTAGE) * STAGE_BYTES;
        const uint32_t sB = sA + TILE_BYTES;

        unsigned a[2][4][4], b[2][8][2];
        LOAD_FRAGS(0, 0);
#pragma unroll
        for (int ks = 0; ks < 4; ks++) {
            const int cur = ks & 1;
            if (ks < 3) LOAD_FRAGS(cur ^ 1, ks + 1);
#pragma unroll
            for (int mi = 0; mi < 4; mi++)
#pragma unroll
                for (int ni = 0; ni < 8; ni++)
                    MMA_F16(acc[mi][ni], a[cur][mi], b[cur][ni]);
        }
    }

    if (MODE == 0) {
        __half* Ch = (__half*)Cout;
#pragma unroll
        for (int mi = 0; mi < 4; mi++) {
#pragma unroll
            for (int ni = 0; ni < 8; ni++) {
                int r  = row0 + wm * 64 + mi * 16 + gid;
                int cl = col0 + wn * 64 + ni * 8 + 2 * tg;
                float b0 = __ldg(bias + cl), b1 = __ldg(bias + cl + 1);
                float v0 = fmaxf(acc[mi][ni][0] + b0, 0.f);
                float v1 = fmaxf(acc[mi][ni][1] + b1, 0.f);
                float v2 = fmaxf(acc[mi][ni][2] + b0, 0.f);
                float v3 = fmaxf(acc[mi][ni][3] + b1, 0.f);
                *(__half2*)(Ch + (size_t)r * N + cl)       = __floats2half2_rn(v0, v1);
                *(__half2*)(Ch + (size_t)(r + 8) * N + cl) = __floats2half2_rn(v2, v3);
            }
        }
    } else {
        // relu(. + bias) then dot with wo slice -> per-row partial
        float* sred = (float*)smem;
        __syncthreads();
        if (tid < BM) sred[tid] = 0.f;
        __syncthreads();
#pragma unroll
        for (int mi = 0; mi < 4; mi++) {
            float s0 = 0.f, s1 = 0.f;
#pragma unroll
            for (int ni = 0; ni < 8; ni++) {
                int cl = wn * 64 + ni * 8 + 2 * tg;
                float w0 = __ldg(wo + col0 + cl), w1 = __ldg(wo + col0 + cl + 1);
                float b0 = __ldg(bias + col0 + cl), b1 = __ldg(bias + col0 + cl + 1);
                s0 += fmaxf(acc[mi][ni][0] + b0, 0.f) * w0 +
                      fmaxf(acc[mi][ni][1] + b1, 0.f) * w1;
                s1 += fmaxf(acc[mi][ni][2] + b0, 0.f) * w0 +
                      fmaxf(acc[mi][ni][3] + b1, 0.f) * w1;
            }
            int rl = wm * 64 + mi * 16 + gid;
            atomicAdd(&sred[rl], s0);
            atomicAdd(&sred[rl + 8], s1);
        }
        __syncthreads();
        if (tid < BM) {
            float* Pf = (float*)Cout;
            Pf[(size_t)blockIdx.x * BATCH + row0 + tid] = sred[tid];
        }
    }
}

// ---------------------------------------------------------------------------
// Final: out[b] = sum of 4 column partials + bo
// ---------------------------------------------------------------------------
__global__ void final_kernel(const float* __restrict__ partial,
                             const float* __restrict__ bo,
                             float* __restrict__ out) {
    int i = blockIdx.x * blockDim.x + threadIdx.x;
    if (i >= BATCH) return;
    out[i] = partial[i] + partial[BATCH + i] + partial[2 * BATCH + i] +
             partial[3 * BATCH + i] + bo[0];
}

// ---------------------------------------------------------------------------
extern "C" void kernel_launch(void* const* d_in, const int* in_sizes, int n_in,
                              void* d_out, int out_size) {
    (void)in_sizes; (void)n_in; (void)out_size;
    const float* x  = (const float*)d_in[0];
    const float* cw = (const float*)d_in[1];
    const float* cb = (const float*)d_in[2];
    const float* W1 = (const float*)d_in[3];  const float* b1 = (const float*)d_in[4];
    const float* W2 = (const float*)d_in[5];  const float* b2 = (const float*)d_in[6];
    const float* W3 = (const float*)d_in[7];  const float* b3 = (const float*)d_in[8];
    const float* W4 = (const float*)d_in[9];  const float* b4 = (const float*)d_in[10];
    const float* Wo = (const float*)d_in[11]; const float* bo = (const float*)d_in[12];

    float *buf0, *buf1, *w1f, *w2f, *w3f, *w4f;
    cudaGetSymbolAddress((void**)&buf0, g_buf0);
    cudaGetSymbolAddress((void**)&buf1, g_buf1);
    cudaGetSymbolAddress((void**)&w1f, g_w1);
    cudaGetSymbolAddress((void**)&w2f, g_w2);
    cudaGetSymbolAddress((void**)&w3f, g_w3);
    cudaGetSymbolAddress((void**)&w4f, g_w4);
    __half* h0 = (__half*)buf0;
    __half* h1 = (__half*)buf1;
    __half* w1 = (__half*)w1f;  __half* w2 = (__half*)w2f;
    __half* w3 = (__half*)w3f;  __half* w4 = (__half*)w4f;

    static int smem_set = 0;
    if (!smem_set) {
        cudaFuncSetAttribute(gemm_f16<0>,
                             cudaFuncAttributeMaxDynamicSharedMemorySize, SMEM_BYTES);
        cudaFuncSetAttribute(gemm_f16<1>,
                             cudaFuncAttributeMaxDynamicSharedMemorySize, SMEM_BYTES);
        smem_set = 1;
    }

    cvt_all_kernel<<<(N4_TOTAL + 255) / 256, 256>>>(W1, W2, W3, W4, w1, w2, w3, w4);

    cross_kernel<<<BATCH / 8, 256>>>(x, cw, cb, h0);

    gemm_f16<0><<<dim3(2048 / BN, BATCH / BM), 128, SMEM_BYTES>>>(h0, w1, b1, h1, nullptr,  512, 2048);
    gemm_f16<0><<<dim3(2048 / BN, BATCH / BM), 128, SMEM_BYTES>>>(h1, w2, b2, h0, nullptr, 2048, 2048);
    gemm_f16<0><<<dim3(1024 / BN, BATCH / BM), 128, SMEM_BYTES>>>(h0, w3, b3, h1, nullptr, 2048, 1024);
    // GEMM4 fused with head: 4 column partials into buf0
    gemm_f16<1><<<dim3( 512 / BN, BATCH / BM), 128, SMEM_BYTES>>>(h1, w4, b4, buf0, Wo, 1024, 512);

    final_kernel<<<(BATCH + 255) / 256, 256>>>(buf0, bo, (float*)d_out);
}

// round 17
// speedup vs baseline: 1.0560x; 1.0560x over previous
#include <cuda_runtime.h>
#include <cuda_fp16.h>
#include <cstdint>

#define BATCH 16384
#define IN_F  512

// Ping-pong scratch (raw, reinterpreted as half or float) + fp16 weights.
__device__ float g_buf0[BATCH * 2048];
__device__ float g_buf1[BATCH * 2048];
__device__ float g_w1[2048 * 512];
__device__ float g_w2[2048 * 2048];
__device__ float g_w3[1024 * 2048];
__device__ float g_w4[512 * 1024];

__device__ __forceinline__ uint32_t smem_u32(const void* p) {
    uint32_t a;
    asm("{ .reg .u64 t; cvta.to.shared.u64 t, %1; cvt.u32.u64 %0, t; }"
        : "=r"(a) : "l"(p));
    return a;
}

// ---------------------------------------------------------------------------
// Fused prep kernel: one launch does BOTH (independent, memory-bound jobs):
//   blocks [0, CROSS_BLOCKS)  : cross layer rows (one warp per row)
//   blocks [CROSS_BLOCKS, ..) : weight fp32->fp16 conversion
// ---------------------------------------------------------------------------
#define N4_W1 (2048 * 512 / 4)
#define N4_W2 (2048 * 2048 / 4)
#define N4_W3 (1024 * 2048 / 4)
#define N4_W4 (512 * 1024 / 4)
#define N4_TOTAL (N4_W1 + N4_W2 + N4_W3 + N4_W4)
#define CROSS_BLOCKS (BATCH / 8)                     // 2048
#define CVT_BLOCKS   ((N4_TOTAL + 255) / 256)        // 7680
#define PREP_BLOCKS  (CROSS_BLOCKS + CVT_BLOCKS)

__global__ void prep_kernel(const float* __restrict__ x,
                            const float* __restrict__ cw,
                            const float* __restrict__ cb,
                            __half* __restrict__ xout,
                            const float* __restrict__ W1,
                            const float* __restrict__ W2,
                            const float* __restrict__ W3,
                            const float* __restrict__ W4,
                            __half* __restrict__ o1, __half* __restrict__ o2,
                            __half* __restrict__ o3, __half* __restrict__ o4) {
    if (blockIdx.x < CROSS_BLOCKS) {
        // ---- cross: h = half( x * (x . cw) + cb + x ), one warp per row ----
        int gw   = (blockIdx.x * blockDim.x + threadIdx.x) >> 5;
        int lane = threadIdx.x & 31;
        const float4* xr  = (const float4*)(x + (size_t)gw * IN_F);
        const float4* cwr = (const float4*)cw;
        float4 xv[4];
        float s = 0.f;
#pragma unroll
        for (int c = 0; c < 4; c++) {
            xv[c] = xr[c * 32 + lane];
            float4 w = cwr[c * 32 + lane];
            s += xv[c].x * w.x + xv[c].y * w.y + xv[c].z * w.z + xv[c].w * w.w;
        }
#pragma unroll
        for (int o = 16; o > 0; o >>= 1) s += __shfl_xor_sync(0xffffffffu, s, o);
        const float4* cbr = (const float4*)cb;
        uint2* outr = (uint2*)(xout + (size_t)gw * IN_F);
#pragma unroll
        for (int c = 0; c < 4; c++) {
            float4 b = cbr[c * 32 + lane];
            __half2 h0 = __floats2half2_rn(fmaf(xv[c].x, s, b.x) + xv[c].x,
                                           fmaf(xv[c].y, s, b.y) + xv[c].y);
            __half2 h1 = __floats2half2_rn(fmaf(xv[c].z, s, b.z) + xv[c].z,
                                           fmaf(xv[c].w, s, b.w) + xv[c].w);
            outr[c * 32 + lane] = make_uint2(*(uint32_t*)&h0, *(uint32_t*)&h1);
        }
    } else {
        // ---- weight convert: float4 -> half4 ----
        int i = (blockIdx.x - CROSS_BLOCKS) * blockDim.x + threadIdx.x;
        if (i >= N4_TOTAL) return;
        const float* in; __half* out; int off;
        if (i < N4_W1)                      { in = W1; out = o1; off = i; }
        else if (i < N4_W1 + N4_W2)         { in = W2; out = o2; off = i - N4_W1; }
        else if (i < N4_W1 + N4_W2 + N4_W3) { in = W3; out = o3; off = i - N4_W1 - N4_W2; }
        else                                { in = W4; out = o4; off = i - N4_W1 - N4_W2 - N4_W3; }
        float4 v = ((const float4*)in)[off];
        __half2 h0 = __floats2half2_rn(v.x, v.y);
        __half2 h1 = __floats2half2_rn(v.z, v.w);
        ((uint2*)out)[off] = make_uint2(*(uint32_t*)&h0, *(uint32_t*)&h1);
    }
}

// ---------------------------------------------------------------------------
// FP16 tensor-core GEMM (fp32 accum), cp.async 3-stage + ldmatrix + SW128.
//   MODE 0: C = relu(A @ W^T + bias) stored as half.
//   MODE 1: partial[cta_x*BATCH + row] = relu(A @ W^T + bias) . wo_slice
// BM=BN=128, BK=64 (128B rows, SW128); 128 threads, 4 warps (2m x 2n),
// warp tile 64x64, m16n8k16. 96KB smem -> 2 CTAs/SM.  (R11-verified mainloop)
// ---------------------------------------------------------------------------
#define BM 128
#define BN 128
#define BK 64
#define NSTAGE 3
#define TILE_BYTES (BM * 128)                    // 16384 per operand
#define STAGE_BYTES (2 * TILE_BYTES)             // 32768
#define SMEM_BYTES (NSTAGE * STAGE_BYTES)        // 98304

#define MMA_F16(c, a, b)                                                      \
    asm volatile(                                                             \
        "mma.sync.aligned.m16n8k16.row.col.f32.f16.f16.f32 "                  \
        "{%0,%1,%2,%3},{%4,%5,%6,%7},{%8,%9},{%0,%1,%2,%3};"                  \
        : "+f"(c[0]), "+f"(c[1]), "+f"(c[2]), "+f"(c[3])                      \
        : "r"(a[0]), "r"(a[1]), "r"(a[2]), "r"(a[3]), "r"(b[0]), "r"(b[1]))

#define LDSM4(r0, r1, r2, r3, addr)                                           \
    asm volatile("ldmatrix.sync.aligned.m8n8.x4.shared.b16 {%0,%1,%2,%3}, [%4];" \
                 : "=r"(r0), "=r"(r1), "=r"(r2), "=r"(r3) : "r"(addr))

#define CP16(dst, src)                                                        \
    asm volatile("cp.async.cg.shared.global [%0], [%1], 16;"                  \
                 :: "r"(dst), "l"(src))

// SW128: 16B chunk c (0..7) of 128B row r -> byte offset
__device__ __forceinline__ uint32_t swz(int r, int c) {
    return (uint32_t)(r * 128 + ((c ^ (r & 7)) * 16));
}

template <int MODE>
__global__ __launch_bounds__(128, 2)
void gemm_f16(const __half* __restrict__ A, const __half* __restrict__ W,
              const float* __restrict__ bias, void* __restrict__ Cout,
              const float* __restrict__ wo, int K, int N) {
    extern __shared__ char smem[];
    const uint32_t sbase = smem_u32(smem);
    const int tid = threadIdx.x;
    const int warp = tid >> 5, lane = tid & 31;
    const int wm = warp >> 1, wn = warp & 1;     // 2x2 grid of 64x64 tiles
    const int gid = lane >> 2, tg = lane & 3;
    const int row0 = blockIdx.y * BM;
    const int col0 = blockIdx.x * BN;

    // cp.async producer coords
    const int pr = tid >> 3;
    const int pc = tid & 7;
    const __half* Abase = A + (size_t)(row0 + pr) * K + pc * 8;
    const __half* Wbase = W + (size_t)(col0 + pr) * K + pc * 8;
    const uint32_t pd = swz(pr, pc);

    // ldmatrix lane coords
    const int arowA = wm * 64 + (lane & 15);                         // + 16*mi
    const int acA   = lane >> 4;                                     // + 2*ks
    const int arowB = wn * 64 + (lane & 7) + ((lane & 16) ? 8 : 0);  // + 16*j
    const int acB   = (lane & 8) ? 1 : 0;                            // + 2*ks

    const int T = K / BK;

#define ISSUE_STAGE(kt)                                                       \
    do {                                                                      \
        uint32_t _sA = sbase + ((kt) % NSTAGE) * STAGE_BYTES;                 \
        uint32_t _sB = _sA + TILE_BYTES;                                      \
        const __half* _Ag = Abase + (size_t)(kt) * BK;                        \
        const __half* _Wg = Wbase + (size_t)(kt) * BK;                        \
        _Pragma("unroll")                                                     \
        for (int i = 0; i < 8; i++) {                                         \
            CP16(_sA + pd + i * 2048, _Ag + (size_t)(16 * i) * K);            \
            CP16(_sB + pd + i * 2048, _Wg + (size_t)(16 * i) * K);            \
        }                                                                     \
        asm volatile("cp.async.commit_group;" ::: "memory");                  \
    } while (0)

    float acc[4][8][4];
#pragma unroll
    for (int mi = 0; mi < 4; mi++)
#pragma unroll
        for (int ni = 0; ni < 8; ni++)
#pragma unroll
            for (int e = 0; e < 4; e++) acc[mi][ni][e] = 0.f;

    ISSUE_STAGE(0);
    ISSUE_STAGE(1);

    for (int kt = 0; kt < T; kt++) {
        if (kt + 1 < T)
            asm volatile("cp.async.wait_group 1;" ::: "memory");
        else
            asm volatile("cp.async.wait_group 0;" ::: "memory");
        __syncthreads();

        if (kt + 2 < T) ISSUE_STAGE(kt + 2);

        const uint32_t sA = sbase + (kt % NSTAGE) * STAGE_BYTES;
        const uint32_t sB = sA + TILE_BYTES;

#pragma unroll
        for (int ks = 0; ks < 4; ks++) {            // four k16 steps per tile
            unsigned a[4][4], b[8][2];
#pragma unroll
            for (int mi = 0; mi < 4; mi++)
                LDSM4(a[mi][0], a[mi][1], a[mi][2], a[mi][3],
                      sA + swz(arowA + 16 * mi, ks * 2 + acA));
#pragma unroll
            for (int j = 0; j < 4; j++)
                LDSM4(b[2 * j][0], b[2 * j][1], b[2 * j + 1][0], b[2 * j + 1][1],
                      sB + swz(arowB + 16 * j, ks * 2 + acB));
#pragma unroll
            for (int mi = 0; mi < 4; mi++)
#pragma unroll
                for (int ni = 0; ni < 8; ni++)
                    MMA_F16(acc[mi][ni], a[mi], b[ni]);
        }
    }

    if (MODE == 0) {
        __half* Ch = (__half*)Cout;
#pragma unroll
        for (int mi = 0; mi < 4; mi++) {
#pragma unroll
            for (int ni = 0; ni < 8; ni++) {
                int r  = row0 + wm * 64 + mi * 16 + gid;
                int cl = col0 + wn * 64 + ni * 8 + 2 * tg;
                float b0 = __ldg(bias + cl), b1 = __ldg(bias + cl + 1);
                float v0 = fmaxf(acc[mi][ni][0] + b0, 0.f);
                float v1 = fmaxf(acc[mi][ni][1] + b1, 0.f);
                float v2 = fmaxf(acc[mi][ni][2] + b0, 0.f);
                float v3 = fmaxf(acc[mi][ni][3] + b1, 0.f);
                *(__half2*)(Ch + (size_t)r * N + cl)       = __floats2half2_rn(v0, v1);
                *(__half2*)(Ch + (size_t)(r + 8) * N + cl) = __floats2half2_rn(v2, v3);
            }
        }
    } else {
        // relu(. + bias) then dot with wo slice -> per-row partial
        float* sred = (float*)smem;
        __syncthreads();
        if (tid < BM) sred[tid] = 0.f;
        __syncthreads();
#pragma unroll
        for (int mi = 0; mi < 4; mi++) {
            float s0 = 0.f, s1 = 0.f;
#pragma unroll
            for (int ni = 0; ni < 8; ni++) {
                int cl = wn * 64 + ni * 8 + 2 * tg;
                float w0 = __ldg(wo + col0 + cl), w1 = __ldg(wo + col0 + cl + 1);
                float b0 = __ldg(bias + col0 + cl), b1 = __ldg(bias + col0 + cl + 1);
                s0 += fmaxf(acc[mi][ni][0] + b0, 0.f) * w0 +
                      fmaxf(acc[mi][ni][1] + b1, 0.f) * w1;
                s1 += fmaxf(acc[mi][ni][2] + b0, 0.f) * w0 +
                      fmaxf(acc[mi][ni][3] + b1, 0.f) * w1;
            }
            int rl = wm * 64 + mi * 16 + gid;
            atomicAdd(&sred[rl], s0);
            atomicAdd(&sred[rl + 8], s1);
        }
        __syncthreads();
        if (tid < BM) {
            float* Pf = (float*)Cout;
            Pf[(size_t)blockIdx.x * BATCH + row0 + tid] = sred[tid];
        }
    }
}

// ---------------------------------------------------------------------------
// Final: out[b] = sum of 4 column partials + bo
// ---------------------------------------------------------------------------
__global__ void final_kernel(const float* __restrict__ partial,
                             const float* __restrict__ bo,
                             float* __restrict__ out) {
    int i = blockIdx.x * blockDim.x + threadIdx.x;
    if (i >= BATCH) return;
    out[i] = partial[i] + partial[BATCH + i] + partial[2 * BATCH + i] +
             partial[3 * BATCH + i] + bo[0];
}

// ---------------------------------------------------------------------------
extern "C" void kernel_launch(void* const* d_in, const int* in_sizes, int n_in,
                              void* d_out, int out_size) {
    (void)in_sizes; (void)n_in; (void)out_size;
    const float* x  = (const float*)d_in[0];
    const float* cw = (const float*)d_in[1];
    const float* cb = (const float*)d_in[2];
    const float* W1 = (const float*)d_in[3];  const float* b1 = (const float*)d_in[4];
    const float* W2 = (const float*)d_in[5];  const float* b2 = (const float*)d_in[6];
    const float* W3 = (const float*)d_in[7];  const float* b3 = (const float*)d_in[8];
    const float* W4 = (const float*)d_in[9];  const float* b4 = (const float*)d_in[10];
    const float* Wo = (const float*)d_in[11]; const float* bo = (const float*)d_in[12];

    float *buf0, *buf1, *w1f, *w2f, *w3f, *w4f;
    cudaGetSymbolAddress((void**)&buf0, g_buf0);
    cudaGetSymbolAddress((void**)&buf1, g_buf1);
    cudaGetSymbolAddress((void**)&w1f, g_w1);
    cudaGetSymbolAddress((void**)&w2f, g_w2);
    cudaGetSymbolAddress((void**)&w3f, g_w3);
    cudaGetSymbolAddress((void**)&w4f, g_w4);
    __half* h0 = (__half*)buf0;
    __half* h1 = (__half*)buf1;
    __half* w1 = (__half*)w1f;  __half* w2 = (__half*)w2f;
    __half* w3 = (__half*)w3f;  __half* w4 = (__half*)w4f;

    static int smem_set = 0;
    if (!smem_set) {
        cudaFuncSetAttribute(gemm_f16<0>,
                             cudaFuncAttributeMaxDynamicSharedMemorySize, SMEM_BYTES);
        cudaFuncSetAttribute(gemm_f16<1>,
                             cudaFuncAttributeMaxDynamicSharedMemorySize, SMEM_BYTES);
        smem_set = 1;
    }

    // one launch: cross rows + all weight conversions (independent jobs)
    prep_kernel<<<PREP_BLOCKS, 256>>>(x, cw, cb, h0,
                                      W1, W2, W3, W4, w1, w2, w3, w4);

    gemm_f16<0><<<dim3(2048 / BN, BATCH / BM), 128, SMEM_BYTES>>>(h0, w1, b1, h1, nullptr,  512, 2048);
    gemm_f16<0><<<dim3(2048 / BN, BATCH / BM), 128, SMEM_BYTES>>>(h1, w2, b2, h0, nullptr, 2048, 2048);
    gemm_f16<0><<<dim3(1024 / BN, BATCH / BM), 128, SMEM_BYTES>>>(h0, w3, b3, h1, nullptr, 2048, 1024);
    // GEMM4 fused with head: 4 column partials into buf0
    gemm_f16<1><<<dim3( 512 / BN, BATCH / BM), 128, SMEM_BYTES>>>(h1, w4, b4, buf0, Wo, 1024, 512);

    final_kernel<<<(BATCH + 255) / 256, 256>>>(buf0, bo, (float*)d_out);
}